// round 9
// baseline (speedup 1.0000x reference)
#include <cuda_runtime.h>
#include <cuda_fp16.h>
#include <cstdint>

#define NNODES 10000
#define NEDGES 160000
#define FDIM   512
#define NGRAPH 64
#define ODIM   128
#define ELLW   64

// Scratch (device globals; no allocation allowed)
__device__ __half g_x16[NNODES * FDIM];     // fp16 input features
__device__ __half g_w1t[FDIM * FDIM];       // W1 transposed [N][K] fp16
__device__ __half g_w2t[FDIM * FDIM];       // W2 transposed [N][K] fp16
__device__ __half g_a16[NNODES * FDIM];     // gemm output (pre-agg)
__device__ __half g_b16[NNODES * FDIM];     // agg1 output (layer-2 input)
__device__ float  g_buf2[NNODES * FDIM];    // agg2 fp32 output (for pool)
__device__ float  g_dinv[NNODES];
__device__ int    g_cnt[NNODES];
__device__ int    g_ell[NNODES * ELLW];
__device__ float  g_pooled[NGRAPH * FDIM];

__device__ __forceinline__ int clampi(int v, int lo, int hi) {
    return v < lo ? lo : (v > hi ? hi : v);
}

__device__ __forceinline__ void mma_f16(float* c, const uint32_t* a, const uint32_t* b) {
    asm volatile(
        "mma.sync.aligned.m16n8k16.row.col.f32.f16.f16.f32 "
        "{%0,%1,%2,%3}, {%4,%5,%6,%7}, {%8,%9}, {%0,%1,%2,%3};"
        : "+f"(c[0]), "+f"(c[1]), "+f"(c[2]), "+f"(c[3])
        : "r"(a[0]), "r"(a[1]), "r"(a[2]), "r"(a[3]), "r"(b[0]), "r"(b[1]));
}

// ---------------------------------------------------------------------------
// Converters
// ---------------------------------------------------------------------------
__global__ void convert_x_kernel(const float* __restrict__ x, __half* __restrict__ x16) {
    int i = blockIdx.x * blockDim.x + threadIdx.x;      // over N*F/4
    if (i >= NNODES * FDIM / 4) return;
    float4 v = ((const float4*)x)[i];
    __half2 h0 = __floats2half2_rn(v.x, v.y);
    __half2 h1 = __floats2half2_rn(v.z, v.w);
    uint2 u;
    u.x = *(uint32_t*)&h0; u.y = *(uint32_t*)&h1;
    ((uint2*)x16)[i] = u;
}

// Coalesced 32x32 smem tile transpose: W[K][N] fp32 -> Wt[N][K] fp16
__global__ void transpose_w_kernel(const float* __restrict__ W, __half* __restrict__ Wt) {
    __shared__ float tile[32][33];
    int k0 = blockIdx.y * 32;
    int n0 = blockIdx.x * 32;
    int tx = threadIdx.x;           // 32
#pragma unroll
    for (int i = threadIdx.y; i < 32; i += 8)
        tile[i][tx] = W[(size_t)(k0 + i) * FDIM + n0 + tx];
    __syncthreads();
#pragma unroll
    for (int i = threadIdx.y; i < 32; i += 8)
        Wt[(size_t)(n0 + i) * FDIM + k0 + tx] = __float2half_rn(tile[tx][i]);
}

// ---------------------------------------------------------------------------
// ELL build: zero counts, scatter edges into fixed-width rows, dinv
// ---------------------------------------------------------------------------
__global__ void zero_cnt_kernel(int* cnt, int n) {
    int i = blockIdx.x * blockDim.x + threadIdx.x;
    if (i < n) cnt[i] = 0;
}

__global__ void scatter_ell_kernel(const int* __restrict__ src, const int* __restrict__ dst,
                                   int* cnt, int* ell, int e) {
    int i = blockIdx.x * blockDim.x + threadIdx.x;
    if (i >= e) return;
    int d = clampi(dst[i], 0, NNODES - 1);
    int s = clampi(src[i], 0, NNODES - 1);
    int slot = atomicAdd(&cnt[d], 1);
    if (slot < ELLW) ell[d * ELLW + slot] = s;
}

__global__ void dinv_kernel(const int* __restrict__ cnt, float* dinv, int n) {
    int i = blockIdx.x * blockDim.x + threadIdx.x;
    if (i < n) dinv[i] = rsqrtf((float)(cnt[i] + 1));   // +1 self loop
}

// ---------------------------------------------------------------------------
// fp16 tensor-core GEMM: C16[M,512] = A16[M,512] @ Bt16[512,512]^T, fp32 accum.
// ---------------------------------------------------------------------------
__global__ void __launch_bounds__(256, 2)
h16_gemm_kernel(const __half* __restrict__ A, const __half* __restrict__ Bt,
                __half* __restrict__ C16, int M) {
    const int K = FDIM, N = FDIM, BK = 32;
    __shared__ __half As[2][128][BK + 8];
    __shared__ __half Bs[2][128][BK + 8];

    int tid = threadIdx.x;
    int lane = tid & 31;
    int wid = tid >> 5;
    int warp_m = wid >> 2;       // 0..1
    int warp_n = wid & 3;        // 0..3

    int bm = blockIdx.y * 128;
    int bn = blockIdx.x * 128;

    int lrow = tid >> 1;         // 0..127
    int lcol = (tid & 1) * 16;   // halves: 0 or 16

    float acc[4][4][4] = {};
    uint4 a_pre[2], b_pre[2];

    const int T = K / BK;        // 16

    // prefetch tile 0
    {
        int gr = bm + lrow;
        a_pre[0] = make_uint4(0, 0, 0, 0);
        a_pre[1] = make_uint4(0, 0, 0, 0);
        if (gr < M) {
            a_pre[0] = *(const uint4*)(A + (size_t)gr * K + lcol);
            a_pre[1] = *(const uint4*)(A + (size_t)gr * K + lcol + 8);
        }
        b_pre[0] = *(const uint4*)(Bt + (size_t)(bn + lrow) * K + lcol);
        b_pre[1] = *(const uint4*)(Bt + (size_t)(bn + lrow) * K + lcol + 8);
        *(uint4*)&As[0][lrow][lcol]     = a_pre[0];
        *(uint4*)&As[0][lrow][lcol + 8] = a_pre[1];
        *(uint4*)&Bs[0][lrow][lcol]     = b_pre[0];
        *(uint4*)&Bs[0][lrow][lcol + 8] = b_pre[1];
    }
    __syncthreads();

    int mrow = warp_m * 64 + (lane >> 2);
    int ncol = warp_n * 32 + (lane >> 2);
    int koff = (lane & 3) * 2;

    for (int t = 0; t < T; t++) {
        int cur = t & 1;
        int nxt = cur ^ 1;
        if (t + 1 < T) {
            int k0 = (t + 1) * BK;
            int gr = bm + lrow;
            a_pre[0] = make_uint4(0, 0, 0, 0);
            a_pre[1] = make_uint4(0, 0, 0, 0);
            if (gr < M) {
                a_pre[0] = *(const uint4*)(A + (size_t)gr * K + k0 + lcol);
                a_pre[1] = *(const uint4*)(A + (size_t)gr * K + k0 + lcol + 8);
            }
            b_pre[0] = *(const uint4*)(Bt + (size_t)(bn + lrow) * K + k0 + lcol);
            b_pre[1] = *(const uint4*)(Bt + (size_t)(bn + lrow) * K + k0 + lcol + 8);
        }

#pragma unroll
        for (int ks = 0; ks < BK; ks += 16) {
            uint32_t af[4][4], bf[4][2];
#pragma unroll
            for (int mi = 0; mi < 4; mi++) {
                int r = mrow + mi * 16;
                af[mi][0] = *(const uint32_t*)&As[cur][r][ks + koff];
                af[mi][1] = *(const uint32_t*)&As[cur][r + 8][ks + koff];
                af[mi][2] = *(const uint32_t*)&As[cur][r][ks + koff + 8];
                af[mi][3] = *(const uint32_t*)&As[cur][r + 8][ks + koff + 8];
            }
#pragma unroll
            for (int ni = 0; ni < 4; ni++) {
                int c = ncol + ni * 8;
                bf[ni][0] = *(const uint32_t*)&Bs[cur][c][ks + koff];
                bf[ni][1] = *(const uint32_t*)&Bs[cur][c][ks + koff + 8];
            }
#pragma unroll
            for (int mi = 0; mi < 4; mi++)
#pragma unroll
                for (int ni = 0; ni < 4; ni++)
                    mma_f16(acc[mi][ni], af[mi], bf[ni]);
        }

        if (t + 1 < T) {
            *(uint4*)&As[nxt][lrow][lcol]     = a_pre[0];
            *(uint4*)&As[nxt][lrow][lcol + 8] = a_pre[1];
            *(uint4*)&Bs[nxt][lrow][lcol]     = b_pre[0];
            *(uint4*)&Bs[nxt][lrow][lcol + 8] = b_pre[1];
        }
        __syncthreads();
    }

    // epilogue: fp16 store
    int col_in_frag = (lane & 3) * 2;
#pragma unroll
    for (int mi = 0; mi < 4; mi++) {
#pragma unroll
        for (int ni = 0; ni < 4; ni++) {
            int r0 = bm + warp_m * 64 + mi * 16 + (lane >> 2);
            int c0 = bn + warp_n * 32 + ni * 8 + col_in_frag;
            if (r0 < M) {
                __half2 h = __floats2half2_rn(acc[mi][ni][0], acc[mi][ni][1]);
                *(__half2*)(C16 + (size_t)r0 * N + c0) = h;
            }
            if (r0 + 8 < M) {
                __half2 h = __floats2half2_rn(acc[mi][ni][2], acc[mi][ni][3]);
                *(__half2*)(C16 + (size_t)(r0 + 8) * N + c0) = h;
            }
        }
    }
}

// ---------------------------------------------------------------------------
// Fused aggregation (fp16 gather & self-loop), fp32 math
// ---------------------------------------------------------------------------
__global__ void __launch_bounds__(128)
fused_agg_kernel(const __half* __restrict__ h16, const float* __restrict__ dinv,
                 const int* __restrict__ cnt, const int* __restrict__ ell,
                 const float* __restrict__ bias,
                 __half* __restrict__ out16, float* __restrict__ out32,
                 int write16, int write32) {
    int grp  = threadIdx.x >> 6;          // 0..1
    int lane = threadIdx.x & 63;          // owns halves [lane*8, lane*8+8)
    int d = blockIdx.x * 2 + grp;

    float dd = dinv[d];
    int deg = min(cnt[d], ELLW);
    const int* erow = ell + (size_t)d * ELLW;

    // self loop (fp16 -> fp32)
    float4 sp = ((const float4*)(h16 + (size_t)d * FDIM))[lane];
    const __half2* sh = (const __half2*)&sp;
    float sdd = dd * dd;
    float2 s0 = __half22float2(sh[0]);
    float2 s1 = __half22float2(sh[1]);
    float2 s2 = __half22float2(sh[2]);
    float2 s3 = __half22float2(sh[3]);
    float acc[8] = { s0.x * sdd, s0.y * sdd, s1.x * sdd, s1.y * sdd,
                     s2.x * sdd, s2.y * sdd, s3.x * sdd, s3.y * sdd };

#pragma unroll 2
    for (int j = 0; j < deg; j++) {
        int s = erow[j];                       // broadcast
        float nrm = dinv[s] * dd;              // cached broadcast load
        float4 p = ((const float4*)(h16 + (size_t)s * FDIM))[lane];
        const __half2* hp = (const __half2*)&p;
        float2 f0 = __half22float2(hp[0]);
        float2 f1 = __half22float2(hp[1]);
        float2 f2 = __half22float2(hp[2]);
        float2 f3 = __half22float2(hp[3]);
        acc[0] += f0.x * nrm; acc[1] += f0.y * nrm;
        acc[2] += f1.x * nrm; acc[3] += f1.y * nrm;
        acc[4] += f2.x * nrm; acc[5] += f2.y * nrm;
        acc[6] += f3.x * nrm; acc[7] += f3.y * nrm;
    }

    const float4* brow = (const float4*)bias;
    float4 b0 = brow[lane * 2];
    float4 b1 = brow[lane * 2 + 1];
    float v[8];
    v[0] = fmaxf(acc[0] + b0.x, 0.f); v[1] = fmaxf(acc[1] + b0.y, 0.f);
    v[2] = fmaxf(acc[2] + b0.z, 0.f); v[3] = fmaxf(acc[3] + b0.w, 0.f);
    v[4] = fmaxf(acc[4] + b1.x, 0.f); v[5] = fmaxf(acc[5] + b1.y, 0.f);
    v[6] = fmaxf(acc[6] + b1.z, 0.f); v[7] = fmaxf(acc[7] + b1.w, 0.f);

    if (write16) {
        __half2 h0 = __floats2half2_rn(v[0], v[1]);
        __half2 h1 = __floats2half2_rn(v[2], v[3]);
        __half2 h2 = __floats2half2_rn(v[4], v[5]);
        __half2 h3 = __floats2half2_rn(v[6], v[7]);
        uint4 u;
        u.x = *(uint32_t*)&h0; u.y = *(uint32_t*)&h1;
        u.z = *(uint32_t*)&h2; u.w = *(uint32_t*)&h3;
        ((uint4*)(out16 + (size_t)d * FDIM))[lane] = u;
    }
    if (write32) {
        float4* orow = (float4*)(out32 + (size_t)d * FDIM);
        orow[lane * 2]     = make_float4(v[0], v[1], v[2], v[3]);
        orow[lane * 2 + 1] = make_float4(v[4], v[5], v[6], v[7]);
    }
}

// ---------------------------------------------------------------------------
// Pooling (batch sorted): one block per (graph, 128-feature strip),
// binary-search the node range, direct sum, no atomics.
// ---------------------------------------------------------------------------
__global__ void pool_kernel(const float* __restrict__ h, const int* __restrict__ batch,
                            float* __restrict__ pooled) {
    int g = blockIdx.x;
    int f = blockIdx.y * 128 + threadIdx.x;

    // lower_bound(batch, g) and lower_bound(batch, g+1)
    int lo = 0, hi = NNODES;
    while (lo < hi) { int mid = (lo + hi) >> 1; if (batch[mid] < g) lo = mid + 1; else hi = mid; }
    int beg = lo;
    hi = NNODES;
    while (lo < hi) { int mid = (lo + hi) >> 1; if (batch[mid] < g + 1) lo = mid + 1; else hi = mid; }
    int end = lo;

    float acc = 0.f;
    for (int n = beg; n < end; n++)
        acc += h[(size_t)n * FDIM + f];
    pooled[g * FDIM + f] = acc;
}

// ---------------------------------------------------------------------------
// Final small GEMM: out[64,128] = pooled[64,512] @ Wlin[512,128] + blin
// ---------------------------------------------------------------------------
__global__ void final_gemm_kernel(const float* __restrict__ pooled,
                                  const float* __restrict__ Wlin,
                                  const float* __restrict__ blin,
                                  float* __restrict__ out) {
    __shared__ float p[FDIM];
    int g = blockIdx.x;
    int o = threadIdx.x;   // 128
    for (int k = o; k < FDIM; k += ODIM) p[k] = pooled[g * FDIM + k];
    __syncthreads();
    float acc = blin[o];
#pragma unroll 8
    for (int k = 0; k < FDIM; k++) acc += p[k] * Wlin[k * ODIM + o];
    out[g * ODIM + o] = acc;
}

// ---------------------------------------------------------------------------
// Launch
// ---------------------------------------------------------------------------
extern "C" void kernel_launch(void* const* d_in, const int* in_sizes, int n_in,
                              void* d_out, int out_size) {
    const float* x    = (const float*)d_in[0];
    const float* W1   = (const float*)d_in[1];
    const float* b1   = (const float*)d_in[2];
    const float* W2   = (const float*)d_in[3];
    const float* b2   = (const float*)d_in[4];
    const float* Wlin = (const float*)d_in[5];
    const float* blin = (const float*)d_in[6];
    const int* edge_index = (const int*)d_in[7];   // harness maps int64 -> int32
    const int* batch      = (const int*)d_in[8];

    const int* src = edge_index;
    const int* dst = edge_index + NEDGES;

    __half *x16, *w1t, *w2t, *a16, *b16;
    float *buf2, *dinv, *pooled_scratch;
    int *cnt, *ell;
    cudaGetSymbolAddress((void**)&x16, g_x16);
    cudaGetSymbolAddress((void**)&w1t, g_w1t);
    cudaGetSymbolAddress((void**)&w2t, g_w2t);
    cudaGetSymbolAddress((void**)&a16, g_a16);
    cudaGetSymbolAddress((void**)&b16, g_b16);
    cudaGetSymbolAddress((void**)&buf2, g_buf2);
    cudaGetSymbolAddress((void**)&dinv, g_dinv);
    cudaGetSymbolAddress((void**)&pooled_scratch, g_pooled);
    cudaGetSymbolAddress((void**)&cnt, g_cnt);
    cudaGetSymbolAddress((void**)&ell, g_ell);

    float* pooled;
    float* out2;
    if (out_size >= NGRAPH * FDIM + NGRAPH * ODIM) {
        pooled = (float*)d_out;
        out2   = (float*)d_out + NGRAPH * FDIM;
    } else {
        pooled = pooled_scratch;
        out2   = (float*)d_out;
    }

    // Side stream for overlapping ELL build + W2 transpose with x-convert/W1/GEMM1.
    static cudaStream_t side = nullptr;
    static cudaEvent_t evFork = nullptr, evJoin = nullptr;
    static bool inited = false;
    if (!inited) {
        inited = true;
        if (cudaStreamCreateWithFlags(&side, cudaStreamNonBlocking) != cudaSuccess)
            side = nullptr;
        if (side) {
            if (cudaEventCreateWithFlags(&evFork, cudaEventDisableTiming) != cudaSuccess ||
                cudaEventCreateWithFlags(&evJoin, cudaEventDisableTiming) != cudaSuccess)
                side = nullptr;
        }
    }

    dim3 gemm_grid(FDIM / 128, (NNODES + 127) / 128);
    dim3 tw_grid(FDIM / 32, FDIM / 32);
    dim3 tw_block(32, 8);

    if (side) {
        cudaEventRecord(evFork, 0);
        cudaStreamWaitEvent(side, evFork, 0);
        zero_cnt_kernel<<<(NNODES + 255) / 256, 256, 0, side>>>(cnt, NNODES);
        scatter_ell_kernel<<<(NEDGES + 255) / 256, 256, 0, side>>>(src, dst, cnt, ell, NEDGES);
        dinv_kernel<<<(NNODES + 255) / 256, 256, 0, side>>>(cnt, dinv, NNODES);
        transpose_w_kernel<<<tw_grid, tw_block, 0, side>>>(W2, w2t);
        cudaEventRecord(evJoin, side);

        convert_x_kernel<<<(NNODES * FDIM / 4 + 255) / 256, 256>>>(x, x16);
        transpose_w_kernel<<<tw_grid, tw_block>>>(W1, w1t);
        h16_gemm_kernel<<<gemm_grid, 256>>>(x16, w1t, a16, NNODES);

        cudaStreamWaitEvent(0, evJoin, 0);
    } else {
        zero_cnt_kernel<<<(NNODES + 255) / 256, 256>>>(cnt, NNODES);
        scatter_ell_kernel<<<(NEDGES + 255) / 256, 256>>>(src, dst, cnt, ell, NEDGES);
        dinv_kernel<<<(NNODES + 255) / 256, 256>>>(cnt, dinv, NNODES);
        transpose_w_kernel<<<tw_grid, tw_block>>>(W2, w2t);
        convert_x_kernel<<<(NNODES * FDIM / 4 + 255) / 256, 256>>>(x, x16);
        transpose_w_kernel<<<tw_grid, tw_block>>>(W1, w1t);
        h16_gemm_kernel<<<gemm_grid, 256>>>(x16, w1t, a16, NNODES);
    }

    // Layer 1 aggregation: fp16 out only (feeds gemm2)
    fused_agg_kernel<<<NNODES / 2, 128>>>(a16, dinv, cnt, ell, b1, b16, nullptr, 1, 0);

    // Layer 2
    h16_gemm_kernel<<<gemm_grid, 256>>>(b16, w2t, a16, NNODES);
    fused_agg_kernel<<<NNODES / 2, 128>>>(a16, dinv, cnt, ell, b2, nullptr, buf2, 0, 1);

    // Pooling (no atomics)
    {
        dim3 pg(NGRAPH, FDIM / 128);
        pool_kernel<<<pg, 128>>>(buf2, batch, pooled);
    }

    // Final linear
    final_gemm_kernel<<<NGRAPH, ODIM>>>(pooled, Wlin, blin, out2);
}

// round 10
// speedup vs baseline: 1.0436x; 1.0436x over previous
#include <cuda_runtime.h>
#include <cuda_fp16.h>
#include <cstdint>

#define NNODES 10000
#define NEDGES 160000
#define FDIM   512
#define NGRAPH 64
#define ODIM   128
#define ELLW   64

// Scratch (device globals; no allocation allowed)
__device__ __half g_x16[NNODES * FDIM];     // fp16 input features
__device__ __half g_w1t[FDIM * FDIM];       // W1 transposed [N][K] fp16
__device__ __half g_w2t[FDIM * FDIM];       // W2 transposed [N][K] fp16
__device__ __half g_a16[NNODES * FDIM];     // gemm output (pre-agg)
__device__ __half g_b16[NNODES * FDIM];     // agg1 output (layer-2 input)
__device__ float  g_buf2[NNODES * FDIM];    // agg2 fp32 output (for pool)
__device__ int    g_cnt[NNODES];
__device__ int    g_ell[NNODES * ELLW];
__device__ float  g_pooled[NGRAPH * FDIM];

__device__ __forceinline__ int clampi(int v, int lo, int hi) {
    return v < lo ? lo : (v > hi ? hi : v);
}

__device__ __forceinline__ void mma_f16(float* c, const uint32_t* a, const uint32_t* b) {
    asm volatile(
        "mma.sync.aligned.m16n8k16.row.col.f32.f16.f16.f32 "
        "{%0,%1,%2,%3}, {%4,%5,%6,%7}, {%8,%9}, {%0,%1,%2,%3};"
        : "+f"(c[0]), "+f"(c[1]), "+f"(c[2]), "+f"(c[3])
        : "r"(a[0]), "r"(a[1]), "r"(a[2]), "r"(a[3]), "r"(b[0]), "r"(b[1]));
}

// ---------------------------------------------------------------------------
// Fused convert + cnt-zero: x -> fp16, W1/W2 -> fp16 transposed [N][K], cnt=0
// ---------------------------------------------------------------------------
__global__ void convert_zero_kernel(const float* __restrict__ x,
                                    const float* __restrict__ W1,
                                    const float* __restrict__ W2,
                                    __half* __restrict__ x16,
                                    __half* __restrict__ w1t,
                                    __half* __restrict__ w2t,
                                    int* __restrict__ cnt) {
    const int XA = NNODES * FDIM / 2;          // half2 count for x
    const int WB = FDIM * FDIM / 2;            // (n, k-pair) count per weight
    int i = blockIdx.x * blockDim.x + threadIdx.x;
    if (i < XA) {
        float2 v = ((const float2*)x)[i];
        ((__half2*)x16)[i] = __floats2half2_rn(v.x, v.y);
    } else if (i < XA + WB) {
        int j = i - XA;
        int n = j >> 8;                         // 0..511
        int k = (j & 255) * 2;                  // 0..510 step 2
        float v0 = W1[(size_t)k * FDIM + n];
        float v1 = W1[(size_t)(k + 1) * FDIM + n];
        ((__half2*)(w1t + (size_t)n * FDIM + k))[0] = __floats2half2_rn(v0, v1);
    } else if (i < XA + 2 * WB) {
        int j = i - XA - WB;
        int n = j >> 8;
        int k = (j & 255) * 2;
        float v0 = W2[(size_t)k * FDIM + n];
        float v1 = W2[(size_t)(k + 1) * FDIM + n];
        ((__half2*)(w2t + (size_t)n * FDIM + k))[0] = __floats2half2_rn(v0, v1);
    } else if (i < XA + 2 * WB + NNODES) {
        cnt[i - XA - 2 * WB] = 0;
    }
}

// ---------------------------------------------------------------------------
// ELL scatter
// ---------------------------------------------------------------------------
__global__ void scatter_ell_kernel(const int* __restrict__ src, const int* __restrict__ dst,
                                   int* cnt, int* ell, int e) {
    int i = blockIdx.x * blockDim.x + threadIdx.x;
    if (i >= e) return;
    int d = clampi(dst[i], 0, NNODES - 1);
    int s = clampi(src[i], 0, NNODES - 1);
    int slot = atomicAdd(&cnt[d], 1);
    if (slot < ELLW) ell[d * ELLW + slot] = s;
}

// ---------------------------------------------------------------------------
// fp16 tensor-core GEMM: C16[M,512] = A16[M,512] @ Bt16[512,512]^T, fp32 accum.
// ---------------------------------------------------------------------------
__global__ void __launch_bounds__(256, 2)
h16_gemm_kernel(const __half* __restrict__ A, const __half* __restrict__ Bt,
                __half* __restrict__ C16, int M) {
    const int K = FDIM, N = FDIM, BK = 32;
    __shared__ __half As[2][128][BK + 8];
    __shared__ __half Bs[2][128][BK + 8];

    int tid = threadIdx.x;
    int lane = tid & 31;
    int wid = tid >> 5;
    int warp_m = wid >> 2;       // 0..1
    int warp_n = wid & 3;        // 0..3

    int bm = blockIdx.y * 128;
    int bn = blockIdx.x * 128;

    int lrow = tid >> 1;         // 0..127
    int lcol = (tid & 1) * 16;   // halves: 0 or 16

    float acc[4][4][4] = {};
    uint4 a_pre[2], b_pre[2];

    const int T = K / BK;        // 16

    // prefetch tile 0
    {
        int gr = bm + lrow;
        a_pre[0] = make_uint4(0, 0, 0, 0);
        a_pre[1] = make_uint4(0, 0, 0, 0);
        if (gr < M) {
            a_pre[0] = *(const uint4*)(A + (size_t)gr * K + lcol);
            a_pre[1] = *(const uint4*)(A + (size_t)gr * K + lcol + 8);
        }
        b_pre[0] = *(const uint4*)(Bt + (size_t)(bn + lrow) * K + lcol);
        b_pre[1] = *(const uint4*)(Bt + (size_t)(bn + lrow) * K + lcol + 8);
        *(uint4*)&As[0][lrow][lcol]     = a_pre[0];
        *(uint4*)&As[0][lrow][lcol + 8] = a_pre[1];
        *(uint4*)&Bs[0][lrow][lcol]     = b_pre[0];
        *(uint4*)&Bs[0][lrow][lcol + 8] = b_pre[1];
    }
    __syncthreads();

    int mrow = warp_m * 64 + (lane >> 2);
    int ncol = warp_n * 32 + (lane >> 2);
    int koff = (lane & 3) * 2;

    for (int t = 0; t < T; t++) {
        int cur = t & 1;
        int nxt = cur ^ 1;
        if (t + 1 < T) {
            int k0 = (t + 1) * BK;
            int gr = bm + lrow;
            a_pre[0] = make_uint4(0, 0, 0, 0);
            a_pre[1] = make_uint4(0, 0, 0, 0);
            if (gr < M) {
                a_pre[0] = *(const uint4*)(A + (size_t)gr * K + k0 + lcol);
                a_pre[1] = *(const uint4*)(A + (size_t)gr * K + k0 + lcol + 8);
            }
            b_pre[0] = *(const uint4*)(Bt + (size_t)(bn + lrow) * K + k0 + lcol);
            b_pre[1] = *(const uint4*)(Bt + (size_t)(bn + lrow) * K + k0 + lcol + 8);
        }

#pragma unroll
        for (int ks = 0; ks < BK; ks += 16) {
            uint32_t af[4][4], bf[4][2];
#pragma unroll
            for (int mi = 0; mi < 4; mi++) {
                int r = mrow + mi * 16;
                af[mi][0] = *(const uint32_t*)&As[cur][r][ks + koff];
                af[mi][1] = *(const uint32_t*)&As[cur][r + 8][ks + koff];
                af[mi][2] = *(const uint32_t*)&As[cur][r][ks + koff + 8];
                af[mi][3] = *(const uint32_t*)&As[cur][r + 8][ks + koff + 8];
            }
#pragma unroll
            for (int ni = 0; ni < 4; ni++) {
                int c = ncol + ni * 8;
                bf[ni][0] = *(const uint32_t*)&Bs[cur][c][ks + koff];
                bf[ni][1] = *(const uint32_t*)&Bs[cur][c][ks + koff + 8];
            }
#pragma unroll
            for (int mi = 0; mi < 4; mi++)
#pragma unroll
                for (int ni = 0; ni < 4; ni++)
                    mma_f16(acc[mi][ni], af[mi], bf[ni]);
        }

        if (t + 1 < T) {
            *(uint4*)&As[nxt][lrow][lcol]     = a_pre[0];
            *(uint4*)&As[nxt][lrow][lcol + 8] = a_pre[1];
            *(uint4*)&Bs[nxt][lrow][lcol]     = b_pre[0];
            *(uint4*)&Bs[nxt][lrow][lcol + 8] = b_pre[1];
        }
        __syncthreads();
    }

    // epilogue: fp16 store
    int col_in_frag = (lane & 3) * 2;
#pragma unroll
    for (int mi = 0; mi < 4; mi++) {
#pragma unroll
        for (int ni = 0; ni < 4; ni++) {
            int r0 = bm + warp_m * 64 + mi * 16 + (lane >> 2);
            int c0 = bn + warp_n * 32 + ni * 8 + col_in_frag;
            if (r0 < M) {
                __half2 h = __floats2half2_rn(acc[mi][ni][0], acc[mi][ni][1]);
                *(__half2*)(C16 + (size_t)r0 * N + c0) = h;
            }
            if (r0 + 8 < M) {
                __half2 h = __floats2half2_rn(acc[mi][ni][2], acc[mi][ni][3]);
                *(__half2*)(C16 + (size_t)(r0 + 8) * N + c0) = h;
            }
        }
    }
}

// ---------------------------------------------------------------------------
// Fused aggregation (fp16 gather, inline rsqrt normalization):
//   v[d,:] = relu( bias + dinv_d^2 * h[d,:] + sum_j dinv_sj*dinv_d*h[s_j,:] )
// dinv_i = rsqrtf(cnt[i]+1). 2 nodes per 128-thread block, 64 threads/node.
// ---------------------------------------------------------------------------
__global__ void __launch_bounds__(128)
fused_agg_kernel(const __half* __restrict__ h16, const int* __restrict__ cnt,
                 const int* __restrict__ ell, const float* __restrict__ bias,
                 __half* __restrict__ out16, float* __restrict__ out32,
                 int write16, int write32) {
    int grp  = threadIdx.x >> 6;          // 0..1
    int lane = threadIdx.x & 63;          // owns halves [lane*8, lane*8+8)
    int d = blockIdx.x * 2 + grp;

    int cd = cnt[d];
    float dd = rsqrtf((float)(cd + 1));
    int deg = min(cd, ELLW);
    const int* erow = ell + (size_t)d * ELLW;

    // self loop (fp16 -> fp32)
    float4 sp = ((const float4*)(h16 + (size_t)d * FDIM))[lane];
    const __half2* sh = (const __half2*)&sp;
    float sdd = dd * dd;
    float2 s0 = __half22float2(sh[0]);
    float2 s1 = __half22float2(sh[1]);
    float2 s2 = __half22float2(sh[2]);
    float2 s3 = __half22float2(sh[3]);
    float acc[8] = { s0.x * sdd, s0.y * sdd, s1.x * sdd, s1.y * sdd,
                     s2.x * sdd, s2.y * sdd, s3.x * sdd, s3.y * sdd };

#pragma unroll 2
    for (int j = 0; j < deg; j++) {
        int s = erow[j];                                  // broadcast
        float nrm = rsqrtf((float)(cnt[s] + 1)) * dd;     // broadcast + MUFU
        float4 p = ((const float4*)(h16 + (size_t)s * FDIM))[lane];
        const __half2* hp = (const __half2*)&p;
        float2 f0 = __half22float2(hp[0]);
        float2 f1 = __half22float2(hp[1]);
        float2 f2 = __half22float2(hp[2]);
        float2 f3 = __half22float2(hp[3]);
        acc[0] += f0.x * nrm; acc[1] += f0.y * nrm;
        acc[2] += f1.x * nrm; acc[3] += f1.y * nrm;
        acc[4] += f2.x * nrm; acc[5] += f2.y * nrm;
        acc[6] += f3.x * nrm; acc[7] += f3.y * nrm;
    }

    const float4* brow = (const float4*)bias;
    float4 b0 = brow[lane * 2];
    float4 b1 = brow[lane * 2 + 1];
    float v[8];
    v[0] = fmaxf(acc[0] + b0.x, 0.f); v[1] = fmaxf(acc[1] + b0.y, 0.f);
    v[2] = fmaxf(acc[2] + b0.z, 0.f); v[3] = fmaxf(acc[3] + b0.w, 0.f);
    v[4] = fmaxf(acc[4] + b1.x, 0.f); v[5] = fmaxf(acc[5] + b1.y, 0.f);
    v[6] = fmaxf(acc[6] + b1.z, 0.f); v[7] = fmaxf(acc[7] + b1.w, 0.f);

    if (write16) {
        __half2 h0 = __floats2half2_rn(v[0], v[1]);
        __half2 h1 = __floats2half2_rn(v[2], v[3]);
        __half2 h2 = __floats2half2_rn(v[4], v[5]);
        __half2 h3 = __floats2half2_rn(v[6], v[7]);
        uint4 u;
        u.x = *(uint32_t*)&h0; u.y = *(uint32_t*)&h1;
        u.z = *(uint32_t*)&h2; u.w = *(uint32_t*)&h3;
        ((uint4*)(out16 + (size_t)d * FDIM))[lane] = u;
    }
    if (write32) {
        float4* orow = (float4*)(out32 + (size_t)d * FDIM);
        orow[lane * 2]     = make_float4(v[0], v[1], v[2], v[3]);
        orow[lane * 2 + 1] = make_float4(v[4], v[5], v[6], v[7]);
    }
}

// ---------------------------------------------------------------------------
// Fused pool + final linear: one block per graph.
//   pooled[g,:] = sum over node range (batch sorted, binary search)
//   out[g,:]    = pooled[g,:] @ Wlin + blin
// ---------------------------------------------------------------------------
__global__ void __launch_bounds__(128)
pool_final_kernel(const float* __restrict__ h, const int* __restrict__ batch,
                  const float* __restrict__ Wlin, const float* __restrict__ blin,
                  float* __restrict__ pooled, float* __restrict__ out) {
    __shared__ float p[FDIM];
    int g = blockIdx.x;
    int tid = threadIdx.x;   // 128

    // node range for graph g
    int lo = 0, hi = NNODES;
    while (lo < hi) { int mid = (lo + hi) >> 1; if (batch[mid] < g) lo = mid + 1; else hi = mid; }
    int beg = lo;
    hi = NNODES;
    while (lo < hi) { int mid = (lo + hi) >> 1; if (batch[mid] < g + 1) lo = mid + 1; else hi = mid; }
    int end = lo;

    float a0 = 0.f, a1 = 0.f, a2 = 0.f, a3 = 0.f;
    for (int n = beg; n < end; n++) {
        const float* hr = h + (size_t)n * FDIM;
        a0 += hr[tid];
        a1 += hr[tid + 128];
        a2 += hr[tid + 256];
        a3 += hr[tid + 384];
    }
    p[tid] = a0; p[tid + 128] = a1; p[tid + 256] = a2; p[tid + 384] = a3;
    pooled[g * FDIM + tid]       = a0;
    pooled[g * FDIM + tid + 128] = a1;
    pooled[g * FDIM + tid + 256] = a2;
    pooled[g * FDIM + tid + 384] = a3;
    __syncthreads();

    float acc = blin[tid];
#pragma unroll 8
    for (int k = 0; k < FDIM; k++) acc += p[k] * Wlin[k * ODIM + tid];
    out[g * ODIM + tid] = acc;
}

// ---------------------------------------------------------------------------
// Launch
// ---------------------------------------------------------------------------
extern "C" void kernel_launch(void* const* d_in, const int* in_sizes, int n_in,
                              void* d_out, int out_size) {
    const float* x    = (const float*)d_in[0];
    const float* W1   = (const float*)d_in[1];
    const float* b1   = (const float*)d_in[2];
    const float* W2   = (const float*)d_in[3];
    const float* b2   = (const float*)d_in[4];
    const float* Wlin = (const float*)d_in[5];
    const float* blin = (const float*)d_in[6];
    const int* edge_index = (const int*)d_in[7];   // harness maps int64 -> int32
    const int* batch      = (const int*)d_in[8];

    const int* src = edge_index;
    const int* dst = edge_index + NEDGES;

    __half *x16, *w1t, *w2t, *a16, *b16;
    float *buf2, *pooled_scratch;
    int *cnt, *ell;
    cudaGetSymbolAddress((void**)&x16, g_x16);
    cudaGetSymbolAddress((void**)&w1t, g_w1t);
    cudaGetSymbolAddress((void**)&w2t, g_w2t);
    cudaGetSymbolAddress((void**)&a16, g_a16);
    cudaGetSymbolAddress((void**)&b16, g_b16);
    cudaGetSymbolAddress((void**)&buf2, g_buf2);
    cudaGetSymbolAddress((void**)&pooled_scratch, g_pooled);
    cudaGetSymbolAddress((void**)&cnt, g_cnt);
    cudaGetSymbolAddress((void**)&ell, g_ell);

    float* pooled;
    float* out2;
    if (out_size >= NGRAPH * FDIM + NGRAPH * ODIM) {
        pooled = (float*)d_out;
        out2   = (float*)d_out + NGRAPH * FDIM;
    } else {
        pooled = pooled_scratch;
        out2   = (float*)d_out;
    }

    // Side stream: scatter overlapped with GEMM1 (capturable fork/join).
    static cudaStream_t side = nullptr;
    static cudaEvent_t evFork = nullptr, evJoin = nullptr;
    static bool inited = false;
    if (!inited) {
        inited = true;
        if (cudaStreamCreateWithFlags(&side, cudaStreamNonBlocking) != cudaSuccess)
            side = nullptr;
        if (side) {
            if (cudaEventCreateWithFlags(&evFork, cudaEventDisableTiming) != cudaSuccess ||
                cudaEventCreateWithFlags(&evJoin, cudaEventDisableTiming) != cudaSuccess)
                side = nullptr;
        }
    }

    const int CONV_TOTAL = NNODES * FDIM / 2 + FDIM * FDIM + NNODES;
    dim3 gemm_grid(FDIM / 128, (NNODES + 127) / 128);

    // 1. convert + zero cnt (main) — must precede scatter and gemm1
    convert_zero_kernel<<<(CONV_TOTAL + 255) / 256, 256>>>(x, W1, W2, x16, w1t, w2t, cnt);

    if (side) {
        cudaEventRecord(evFork, 0);
        cudaStreamWaitEvent(side, evFork, 0);
        // 2. scatter on side stream, overlapped with gemm1
        scatter_ell_kernel<<<(NEDGES + 255) / 256, 256, 0, side>>>(src, dst, cnt, ell, NEDGES);
        cudaEventRecord(evJoin, side);
        // 3. gemm1 (main)
        h16_gemm_kernel<<<gemm_grid, 256>>>(x16, w1t, a16, NNODES);
        cudaStreamWaitEvent(0, evJoin, 0);
    } else {
        scatter_ell_kernel<<<(NEDGES + 255) / 256, 256>>>(src, dst, cnt, ell, NEDGES);
        h16_gemm_kernel<<<gemm_grid, 256>>>(x16, w1t, a16, NNODES);
    }

    // 4. agg1 (profiled slot)
    fused_agg_kernel<<<NNODES / 2, 128>>>(a16, cnt, ell, b1, b16, nullptr, 1, 0);

    // 5-6. Layer 2
    h16_gemm_kernel<<<gemm_grid, 256>>>(b16, w2t, a16, NNODES);
    fused_agg_kernel<<<NNODES / 2, 128>>>(a16, cnt, ell, b2, nullptr, buf2, 0, 1);

    // 7. fused pool + final linear
    pool_final_kernel<<<NGRAPH, 128>>>(buf2, batch, Wlin, blin, pooled, out2);
}